// round 6
// baseline (speedup 1.0000x reference)
#include <cuda_runtime.h>

// Grid constants (from reference PolarVoxelizer)
#define FOV_HALF 1.134f
#define NUM_A 192
#define NUM_R 320
#define R_MIN 2.7f
#define R_MAX 165.0f
#define Z_DEPTH 100
// Problem shape (fixed per dataset)
#define BATCH 2
#define SEQ 3
#define NPTS 250000

// ---------------------------------------------------------------------------
// Kernel 1: zero the output grid (73.7 MB). float4 stores, one elem/thread.
// ---------------------------------------------------------------------------
__global__ void pv_zero_kernel(float4* __restrict__ out4, int n4,
                               float* __restrict__ out, int n_tail_start, int n_total) {
    int i = blockIdx.x * blockDim.x + threadIdx.x;
    if (i < n4) {
        out4[i] = make_float4(0.f, 0.f, 0.f, 0.f);
    }
    // tail (out_size not divisible by 4) — handled by first few threads
    int t = n_tail_start + i;
    if (i < 4 && t < n_total) {
        out[t] = 0.f;
    }
}

// ---------------------------------------------------------------------------
// Kernel 2: scatter. Only batch 0 contributes to the sliced output.
// searchsorted side='left' == lower_bound (count of bins < value).
// Writes are idempotent (set 1.0f) -> plain stores, no atomics.
// ---------------------------------------------------------------------------
__device__ __forceinline__ int lower_bound_s(const float* __restrict__ a, int n, float v) {
    int lo = 0, hi = n;
    #pragma unroll 4
    while (lo < hi) {
        int m = (lo + hi) >> 1;
        if (a[m] < v) lo = m + 1; else hi = m;
    }
    return lo;
}

__global__ void pv_scatter_kernel(const float* __restrict__ lidars,
                                  const float* __restrict__ r_bins,
                                  const float* __restrict__ a_bins,
                                  float* __restrict__ out, int npts) {
    __shared__ float s_r[NUM_R];
    __shared__ float s_a[NUM_A];
    for (int i = threadIdx.x; i < NUM_R; i += blockDim.x) s_r[i] = r_bins[i];
    for (int i = threadIdx.x; i < NUM_A; i += blockDim.x) s_a[i] = a_bins[i];
    __syncthreads();

    int i = blockIdx.x * blockDim.x + threadIdx.x;
    if (i >= npts) return;

    // batch 0 occupies the first SEQ*NPTS points; layout [B,S,N,3] contiguous
    float x = lidars[3 * i + 0];
    float y = lidars[3 * i + 1];
    float z = lidars[3 * i + 2];

    // Match XLA lowering exactly: no fp contraction, IEEE sqrt/div.
    float ang = atan2f(y, x);                                   // libdevice __nv_atan2f
    float r2  = __fadd_rn(__fmul_rn(x, x), __fmul_rn(y, y));
    float rad = __fsqrt_rn(r2);

    bool mask = (fabsf(ang) < FOV_HALF) & (rad < R_MAX) & (rad > R_MIN);
    if (!mask) return;

    int xg = lower_bound_s(s_r, NUM_R, rad);
    int yg = lower_bound_s(s_a, NUM_A, ang);
    // zg = floor((z - (-2.0)) / 0.2), IEEE division to match reference
    float zf = floorf(__fdiv_rn(__fadd_rn(z, 2.0f), 0.2f));
    int zg = (int)zf;

    // Replicate scatter mode='drop' for the b==0 slice
    if ((unsigned)zg >= (unsigned)Z_DEPTH) return;
    if ((unsigned)yg >= (unsigned)NUM_A)   return;
    if ((unsigned)xg >= (unsigned)NUM_R)   return;

    int s = i / NPTS;                        // sequence index within batch 0
    int lin = (((s * Z_DEPTH + zg) * NUM_A) + yg) * NUM_R + xg;
    out[lin] = 1.0f;
}

// ---------------------------------------------------------------------------
extern "C" void kernel_launch(void* const* d_in, const int* in_sizes, int n_in,
                              void* d_out, int out_size) {
    const float* lidars  = (const float*)d_in[0];   // [B,S,N,3] f32
    const float* r_bins  = (const float*)d_in[1];   // [320]
    const float* a_bins  = (const float*)d_in[2];   // [192]
    float* out = (float*)d_out;                     // [S*Z, A, R] f32 (batch 0 slice)

    // 1) zero the grid
    int n4 = out_size >> 2;
    int tail_start = n4 << 2;
    {
        int threads = 256;
        int blocks = (n4 + threads - 1) / threads;
        pv_zero_kernel<<<blocks, threads>>>((float4*)out, n4, out, tail_start, out_size);
    }

    // 2) scatter batch-0 points
    int npts_b0 = SEQ * NPTS;   // 750000; batch 1 never touches the output slice
    {
        int threads = 256;
        int blocks = (npts_b0 + threads - 1) / threads;
        pv_scatter_kernel<<<blocks, threads>>>(lidars, r_bins, a_bins, out, npts_b0);
    }
}